// round 15
// baseline (speedup 1.0000x reference)
#include <cuda_runtime.h>
#include <cstdint>

#define R        128
#define R3       (R * R * R)
#define BATCH    2
#define NV_TOT   7700
#define NSURF_N  6890
#define NT_TOT   30000
#define EPS_W    0.001f
#define INV2SIG2 200.0f   // 1/(2*0.05^2)

#define TPB          256
#define TETS_PER_BLK 8                                  // one warp per tet
#define TET_BLOCKS_B ((NT_TOT + TETS_PER_BLK - 1) / TETS_PER_BLK)  // 3750/batch
// Interleaved grid per batch: every 3 blocks = 1 tet block + 2 splat slots.
// splat capacity = 2*3750 = 7500 >= 6890 vertices.
#define WORK_BLOCKS_B (TET_BLOCKS_B * 3)                // 11250

// Scratch, zero at module load. INVARIANT: all-zero on entry; finalize of
// each batch restores its half after reading.
// acc = (sem0, sem1, sem2, wsum) -- EPS_W baseline applied in finalize.
__device__ unsigned char g_occ[BATCH * R3];
__device__ float4        g_acc[BATCH * R3];

__device__ __forceinline__ void red_add_f32x4(float4* addr, float x, float y,
                                              float z, float w) {
    asm volatile("red.global.add.v4.f32 [%0], {%1, %2, %3, %4};"
                 :: "l"(addr), "f"(x), "f"(y), "f"(z), "f"(w)
                 : "memory");
}

// ---------------------------------------------------------------------------
// tet occupancy, warp-granular: one warp per tet of batch b.
// Barycentric gradients g1,g2,g3 precomputed once; each test = 3 dots.
// ---------------------------------------------------------------------------
__device__ __forceinline__ void tet_work(int b, int t, int lane,
                                         const float* __restrict__ verts,
                                         const int*   __restrict__ tets) {
    int4 ti = ((const int4*)tets)[t];
    const float* vb = verts + (size_t)b * NV_TOT * 3;
    const float* p0 = vb + (size_t)ti.x * 3;
    const float* p1 = vb + (size_t)ti.y * 3;
    const float* p2 = vb + (size_t)ti.z * 3;
    const float* p3 = vb + (size_t)ti.w * 3;

    float ax = p0[0], ay = p0[1], az = p0[2];
    float bxv = p1[0], byv = p1[1], bzv = p1[2];
    float cxv = p2[0], cyv = p2[1], czv = p2[2];
    float dxv = p3[0], dyv = p3[1], dzv = p3[2];

    float e1x = bxv - ax, e1y = byv - ay, e1z = bzv - az;
    float e2x = cxv - ax, e2y = cyv - ay, e2z = czv - az;
    float e3x = dxv - ax, e3y = dyv - ay, e3z = dzv - az;

    float c23x = e2y * e3z - e2z * e3y;
    float c23y = e2z * e3x - e2x * e3z;
    float c23z = e2x * e3y - e2y * e3x;

    float vol6 = e1x * c23x + e1y * c23y + e1z * c23z;
    if (!(fabsf(vol6) > 1e-12f)) return;
    float iv = 1.0f / vol6;

    float g1x = c23x * iv, g1y = c23y * iv, g1z = c23z * iv;
    float g2x = (e3y * e1z - e3z * e1y) * iv;   // cross(e3,e1)*iv
    float g2y = (e3z * e1x - e3x * e1z) * iv;
    float g2z = (e3x * e1y - e3y * e1x) * iv;
    float g3x = (e1y * e2z - e1z * e2y) * iv;   // cross(e1,e2)*iv
    float g3y = (e1z * e2x - e1x * e2z) * iv;
    float g3z = (e1x * e2y - e1y * e2x) * iv;

    int anx  = (int)floorf(fminf(fminf(ax, bxv), fminf(cxv, dxv)) * (float)R);
    int any_ = (int)floorf(fminf(fminf(ay, byv), fminf(cyv, dyv)) * (float)R);
    int anz  = (int)floorf(fminf(fminf(az, bzv), fminf(czv, dzv)) * (float)R);

    unsigned char* occb = g_occ + b * R3;

    #pragma unroll
    for (int k = 0; k < 4; k++) {
        int j = lane + k * 32;
        if (j >= 125) break;
        int t0 = anx + j % 5;                   // x-fastest
        int t1 = any_ + (j / 5) % 5;
        int t2 = anz + j / 25;
        if ((unsigned)t0 >= R || (unsigned)t1 >= R || (unsigned)t2 >= R) continue;

        float px = ((float)t0 + 0.5f) * (1.0f / (float)R) - ax;
        float py = ((float)t1 + 0.5f) * (1.0f / (float)R) - ay;
        float pz = ((float)t2 + 0.5f) * (1.0f / (float)R) - az;

        float l1 = px * g1x + py * g1y + pz * g1z;
        float l2 = px * g2x + py * g2y + pz * g2z;
        float l3 = px * g3x + py * g3y + pz * g3z;

        if (l1 >= 0.0f && l2 >= 0.0f && l3 >= 0.0f && (l1 + l2 + l3) <= 1.0f) {
            occb[(t2 * R + t1) * R + t0] = 1;
        }
    }
}

// ---------------------------------------------------------------------------
// surface splat, block-granular: one vertex of batch b per 256-thread block;
// thread covers voxel j = tid and j = tid + 256 of the 7^3 window.
// ---------------------------------------------------------------------------
__device__ __forceinline__ void splat_voxel(int j, int bx, int by, int bz,
                                            float vx, float vy, float vz,
                                            float c0, float c1, float c2,
                                            float4* __restrict__ accb) {
    int s0 = bx + j % 7 - 3;          // x fastest -> contiguous in memory
    int s1 = by + (j / 7) % 7 - 3;
    int s2 = bz + j / 49 - 3;
    if ((unsigned)s0 >= R || (unsigned)s1 >= R || (unsigned)s2 >= R) return;

    float dx = ((float)s0 + 0.5f) * (1.0f / (float)R) - vx;
    float dy = ((float)s1 + 0.5f) * (1.0f / (float)R) - vy;
    float dz = ((float)s2 + 0.5f) * (1.0f / (float)R) - vz;
    float d2 = dx * dx + dy * dy + dz * dz;
    float w = __expf(-d2 * INV2SIG2);

    int vox = (s2 * R + s1) * R + s0;
    red_add_f32x4(&accb[vox], w * c0, w * c1, w * c2, w);
}

__device__ __forceinline__ void splat_work(int b, int v, int tid,
                                           const float* __restrict__ verts,
                                           const float* __restrict__ code) {
    const float* vp = verts + ((size_t)b * NV_TOT + v) * 3;
    float vx = vp[0], vy = vp[1], vz = vp[2];
    const float* cp = code + ((size_t)b * NSURF_N + v) * 3;
    float c0 = cp[0], c1 = cp[1], c2 = cp[2];

    int bx = (int)floorf(vx * (float)R);
    int by = (int)floorf(vy * (float)R);
    int bz = (int)floorf(vz * (float)R);

    float4* accb = g_acc + b * R3;

    splat_voxel(tid, bx, by, bz, vx, vy, vz, c0, c1, c2, accb);
    if (tid < 343 - TPB)
        splat_voxel(tid + TPB, bx, by, bz, vx, vy, vz, c0, c1, c2, accb);
}

// ---------------------------------------------------------------------------
// per-batch fused work kernel, interleaved 1 tet block : 2 splat blocks.
// ---------------------------------------------------------------------------
__global__ void __launch_bounds__(TPB)
work_kernel(const float* __restrict__ verts,
            const float* __restrict__ code,
            const int*   __restrict__ tets,
            int b) {
    int blk = blockIdx.x;
    int third = blk / 3;
    if (blk - third * 3 == 0) {
        int t = third * TETS_PER_BLK + (threadIdx.x >> 5);
        if (t < NT_TOT)
            tet_work(b, t, threadIdx.x & 31, verts, tets);
    } else {
        int v = blk - third - 1;       // contiguous splat id within batch
        if (v < NSURF_N)
            splat_work(b, v, threadIdx.x, verts, code);
    }
}

// ---------------------------------------------------------------------------
// per-batch finalize: out[b,c,vox] = acc.c / (acc.w + EPS_W) * occ, then
// reset this batch's acc/occ to zero. One 4-voxel group per thread.
// ---------------------------------------------------------------------------
__global__ void finalize_kernel(float* __restrict__ out, int b) {
    int i = blockIdx.x * blockDim.x + threadIdx.x;   // 4-voxel group in batch
    if (i >= R3 / 4) return;
    int vox = i * 4;
    int gidx = b * (R3 / 4) + i;

    uchar4 oc = ((const uchar4*)g_occ)[gidx];
    float4* a = g_acc + (size_t)b * R3 + vox;
    float4 a0 = a[0], a1 = a[1], a2 = a[2], a3 = a[3];

    float s0 = __fdividef((float)oc.x, a0.w + EPS_W);
    float s1 = __fdividef((float)oc.y, a1.w + EPS_W);
    float s2 = __fdividef((float)oc.z, a2.w + EPS_W);
    float s3 = __fdividef((float)oc.w, a3.w + EPS_W);

    float* ob = out + (size_t)b * 3 * R3 + vox;
    __stcs((float4*)(ob),
           make_float4(a0.x * s0, a1.x * s1, a2.x * s2, a3.x * s3));
    __stcs((float4*)(ob + R3),
           make_float4(a0.y * s0, a1.y * s1, a2.y * s2, a3.y * s3));
    __stcs((float4*)(ob + 2 * R3),
           make_float4(a0.z * s0, a1.z * s1, a2.z * s2, a3.z * s3));

    // restore the all-zero invariant for this batch half
    float4 z = make_float4(0.0f, 0.0f, 0.0f, 0.0f);
    a[0] = z; a[1] = z; a[2] = z; a[3] = z;
    ((unsigned int*)g_occ)[gidx] = 0u;
}

// ---------------------------------------------------------------------------
// Pipeline: work_b0 -> { work_b1 (main) || finalize_b0 (side) } -> finalize_b1
// Batches touch disjoint halves of every buffer, so the only dependencies are
// work_bK -> finalize_bK.
// ---------------------------------------------------------------------------
extern "C" void kernel_launch(void* const* d_in, const int* in_sizes, int n_in,
                              void* d_out, int out_size) {
    const float* smpl_vertices = (const float*)d_in[0]; // (2, 7700, 3)
    const float* vertex_code   = (const float*)d_in[1]; // (2, 6890, 3)
    // d_in[2] = face_indices — dead code in the reference, unused.
    const int*   tet_indices   = (const int*)d_in[3];   // (30000, 4)
    float* out = (float*)d_out;                         // (2, 3, 128, 128, 128)

    static cudaStream_t s_side = nullptr;
    static cudaEvent_t  s_evW0 = nullptr, s_evF0 = nullptr;
    if (s_side == nullptr) {
        cudaStreamCreateWithFlags(&s_side, cudaStreamNonBlocking);
        cudaEventCreateWithFlags(&s_evW0, cudaEventDisableTiming);
        cudaEventCreateWithFlags(&s_evF0, cudaEventDisableTiming);
    }

    const int FIN_BLOCKS = (R3 / 4 + TPB - 1) / TPB;    // 2048

    // stage 0: batch-0 work on main stream
    work_kernel<<<WORK_BLOCKS_B, TPB>>>(smpl_vertices, vertex_code,
                                        tet_indices, 0);
    cudaEventRecord(s_evW0, 0);

    // stage 1a: batch-1 work on main (serial after work_b0 on this stream)
    work_kernel<<<WORK_BLOCKS_B, TPB>>>(smpl_vertices, vertex_code,
                                        tet_indices, 1);

    // stage 1b: batch-0 finalize on side stream, concurrent with work_b1
    cudaStreamWaitEvent(s_side, s_evW0, 0);
    finalize_kernel<<<FIN_BLOCKS, TPB, 0, s_side>>>(out, 0);
    cudaEventRecord(s_evF0, s_side);

    // stage 2: batch-1 finalize on main (after work_b1 by stream order)
    finalize_kernel<<<FIN_BLOCKS, TPB>>>(out, 1);

    // join side stream before returning control to the harness
    cudaStreamWaitEvent(0, s_evF0, 0);
}

// round 16
// speedup vs baseline: 1.1038x; 1.1038x over previous
#include <cuda_runtime.h>
#include <cstdint>

#define R        128
#define R3       (R * R * R)
#define BATCH    2
#define NV_TOT   7700
#define NSURF_N  6890
#define NT_TOT   30000
#define N_TETS   (BATCH * NT_TOT)      // 60000
#define EPS_W    0.001f
#define INV2SIG2 200.0f   // 1/(2*0.05^2)

#define TPB          256
#define WORK_BLOCKS  (BATCH * NSURF_N)  // 13780, one vertex per block
#define TETS_PER_BLK 5                  // warps 0..4 each run one tet
                                        // 13780*5 = 68900 slots >= 60000

// Scratch, zero at module load. INVARIANT: both arrays are all-zero on entry
// to kernel_launch; finalize_kernel restores that invariant each call.
// acc = (sem0, sem1, sem2, wsum) -- EPS_W baseline applied in finalize.
__device__ unsigned char g_occ[BATCH * R3];
__device__ float4        g_acc[BATCH * R3];

__device__ __forceinline__ void red_add_f32x4(float4* addr, float x, float y,
                                              float z, float w) {
    asm volatile("red.global.add.v4.f32 [%0], {%1, %2, %3, %4};"
                 :: "l"(addr), "f"(x), "f"(y), "f"(z), "f"(w)
                 : "memory");
}

// ---------------------------------------------------------------------------
// tet occupancy, warp-granular: one warp per (b, tet).
// Barycentric gradients g1,g2,g3 precomputed once; each voxel test = 3 dots.
// ---------------------------------------------------------------------------
__device__ __forceinline__ void tet_work(int gw, int lane,
                                         const float* __restrict__ verts,
                                         const int*   __restrict__ tets) {
    int b = (gw >= NT_TOT) ? 1 : 0;
    int t = gw - b * NT_TOT;

    int4 ti = ((const int4*)tets)[t];
    const float* vb = verts + (size_t)b * NV_TOT * 3;
    const float* p0 = vb + (size_t)ti.x * 3;
    const float* p1 = vb + (size_t)ti.y * 3;
    const float* p2 = vb + (size_t)ti.z * 3;
    const float* p3 = vb + (size_t)ti.w * 3;

    float ax = p0[0], ay = p0[1], az = p0[2];
    float bxv = p1[0], byv = p1[1], bzv = p1[2];
    float cxv = p2[0], cyv = p2[1], czv = p2[2];
    float dxv = p3[0], dyv = p3[1], dzv = p3[2];

    float e1x = bxv - ax, e1y = byv - ay, e1z = bzv - az;
    float e2x = cxv - ax, e2y = cyv - ay, e2z = czv - az;
    float e3x = dxv - ax, e3y = dyv - ay, e3z = dzv - az;

    float c23x = e2y * e3z - e2z * e3y;
    float c23y = e2z * e3x - e2x * e3z;
    float c23z = e2x * e3y - e2y * e3x;

    float vol6 = e1x * c23x + e1y * c23y + e1z * c23z;
    if (!(fabsf(vol6) > 1e-12f)) return;
    float iv = 1.0f / vol6;

    float g1x = c23x * iv, g1y = c23y * iv, g1z = c23z * iv;
    float g2x = (e3y * e1z - e3z * e1y) * iv;   // cross(e3,e1)*iv
    float g2y = (e3z * e1x - e3x * e1z) * iv;
    float g2z = (e3x * e1y - e3y * e1x) * iv;
    float g3x = (e1y * e2z - e1z * e2y) * iv;   // cross(e1,e2)*iv
    float g3y = (e1z * e2x - e1x * e2z) * iv;
    float g3z = (e1x * e2y - e1y * e2x) * iv;

    int anx  = (int)floorf(fminf(fminf(ax, bxv), fminf(cxv, dxv)) * (float)R);
    int any_ = (int)floorf(fminf(fminf(ay, byv), fminf(cyv, dyv)) * (float)R);
    int anz  = (int)floorf(fminf(fminf(az, bzv), fminf(czv, dzv)) * (float)R);

    unsigned char* occb = g_occ + b * R3;

    #pragma unroll
    for (int k = 0; k < 4; k++) {
        int j = lane + k * 32;
        if (j >= 125) break;
        int t0 = anx + j % 5;                   // x-fastest
        int t1 = any_ + (j / 5) % 5;
        int t2 = anz + j / 25;
        if ((unsigned)t0 >= R || (unsigned)t1 >= R || (unsigned)t2 >= R) continue;

        float px = ((float)t0 + 0.5f) * (1.0f / (float)R) - ax;
        float py = ((float)t1 + 0.5f) * (1.0f / (float)R) - ay;
        float pz = ((float)t2 + 0.5f) * (1.0f / (float)R) - az;

        float l1 = px * g1x + py * g1y + pz * g1z;
        float l2 = px * g2x + py * g2y + pz * g2z;
        float l3 = px * g3x + py * g3y + pz * g3z;

        if (l1 >= 0.0f && l2 >= 0.0f && l3 >= 0.0f && (l1 + l2 + l3) <= 1.0f) {
            occb[(t2 * R + t1) * R + t0] = 1;
        }
    }
}

// ---------------------------------------------------------------------------
// surface splat: one (b, vertex) per block; thread covers voxel j = tid and
// j = tid + 256 of the 7^3 window (x-fastest). One no-return float4
// reduction per voxel: (w*c0, w*c1, w*c2, w).
// ---------------------------------------------------------------------------
__device__ __forceinline__ void splat_voxel(int j, int bx, int by, int bz,
                                            float vx, float vy, float vz,
                                            float c0, float c1, float c2,
                                            float4* __restrict__ accb) {
    int s0 = bx + j % 7 - 3;          // x fastest -> contiguous in memory
    int s1 = by + (j / 7) % 7 - 3;
    int s2 = bz + j / 49 - 3;
    if ((unsigned)s0 >= R || (unsigned)s1 >= R || (unsigned)s2 >= R) return;

    float dx = ((float)s0 + 0.5f) * (1.0f / (float)R) - vx;
    float dy = ((float)s1 + 0.5f) * (1.0f / (float)R) - vy;
    float dz = ((float)s2 + 0.5f) * (1.0f / (float)R) - vz;
    float d2 = dx * dx + dy * dy + dz * dz;
    float w = __expf(-d2 * INV2SIG2);

    int vox = (s2 * R + s1) * R + s0;
    red_add_f32x4(&accb[vox], w * c0, w * c1, w * c2, w);
}

// ---------------------------------------------------------------------------
// fused work kernel: every block = one splat vertex (all 256 threads issue
// no-return reductions) + up to 5 tets (warps 0..4, one tet per warp) that
// execute ALU work while the block's splat atomics drain through L2.
// ---------------------------------------------------------------------------
__global__ void __launch_bounds__(TPB)
work_kernel(const float* __restrict__ verts,
            const float* __restrict__ code,
            const int*   __restrict__ tets) {
    int blk = blockIdx.x;
    int tid = threadIdx.x;

    // ---- splat phase: issue the reductions (no-return -> no result stall)
    {
        int b = (blk >= NSURF_N) ? 1 : 0;
        int v = blk - b * NSURF_N;

        const float* vp = verts + ((size_t)b * NV_TOT + v) * 3;
        float vx = vp[0], vy = vp[1], vz = vp[2];
        const float* cp = code + ((size_t)b * NSURF_N + v) * 3;
        float c0 = cp[0], c1 = cp[1], c2 = cp[2];

        int bx = (int)floorf(vx * (float)R);
        int by = (int)floorf(vy * (float)R);
        int bz = (int)floorf(vz * (float)R);

        float4* accb = g_acc + b * R3;

        splat_voxel(tid, bx, by, bz, vx, vy, vz, c0, c1, c2, accb);
        if (tid < 343 - TPB)
            splat_voxel(tid + TPB, bx, by, bz, vx, vy, vz, c0, c1, c2, accb);
    }

    // ---- tet phase: warps 0..4 each process one tet while atomics drain
    int warp = tid >> 5;
    if (warp < TETS_PER_BLK) {
        int gw = blk * TETS_PER_BLK + warp;
        if (gw < N_TETS)
            tet_work(gw, tid & 31, verts, tets);
    }
}

// ---------------------------------------------------------------------------
// finalize (best measured variant): one 4-voxel group per thread.
// out[b,c,vox] = acc.c / (acc.w + EPS_W) * occ, then reset acc/occ to zero.
// ---------------------------------------------------------------------------
__global__ void finalize_kernel(float* __restrict__ out) {
    int i = blockIdx.x * blockDim.x + threadIdx.x;   // 4-voxel group
    if (i >= BATCH * R3 / 4) return;
    int gi  = i * 4;
    int b   = gi >> 21;
    int vox = gi & (R3 - 1);

    uchar4 oc = ((const uchar4*)g_occ)[i];
    float4* a = g_acc + gi;
    float4 a0 = a[0], a1 = a[1], a2 = a[2], a3 = a[3];

    float s0 = __fdividef((float)oc.x, a0.w + EPS_W);
    float s1 = __fdividef((float)oc.y, a1.w + EPS_W);
    float s2 = __fdividef((float)oc.z, a2.w + EPS_W);
    float s3 = __fdividef((float)oc.w, a3.w + EPS_W);

    float* ob = out + (size_t)b * 3 * R3 + vox;
    __stcs((float4*)(ob),
           make_float4(a0.x * s0, a1.x * s1, a2.x * s2, a3.x * s3));
    __stcs((float4*)(ob + R3),
           make_float4(a0.y * s0, a1.y * s1, a2.y * s2, a3.y * s3));
    __stcs((float4*)(ob + 2 * R3),
           make_float4(a0.z * s0, a1.z * s1, a2.z * s2, a3.z * s3));

    // restore the all-zero invariant for the next launch
    float4 z = make_float4(0.0f, 0.0f, 0.0f, 0.0f);
    a[0] = z; a[1] = z; a[2] = z; a[3] = z;
    ((unsigned int*)g_occ)[i] = 0u;
}

// ---------------------------------------------------------------------------
extern "C" void kernel_launch(void* const* d_in, const int* in_sizes, int n_in,
                              void* d_out, int out_size) {
    const float* smpl_vertices = (const float*)d_in[0]; // (2, 7700, 3)
    const float* vertex_code   = (const float*)d_in[1]; // (2, 6890, 3)
    // d_in[2] = face_indices — dead code in the reference, unused.
    const int*   tet_indices   = (const int*)d_in[3];   // (30000, 4)
    float* out = (float*)d_out;                         // (2, 3, 128, 128, 128)

    work_kernel<<<WORK_BLOCKS, TPB>>>(smpl_vertices, vertex_code, tet_indices);
    {
        int n = BATCH * R3 / 4;
        finalize_kernel<<<(n + TPB - 1) / TPB, TPB>>>(out);
    }
}

// round 17
// speedup vs baseline: 1.1705x; 1.0604x over previous
#include <cuda_runtime.h>
#include <cstdint>

#define R        128
#define R3       (R * R * R)
#define BATCH    2
#define NV_TOT   7700
#define NSURF_N  6890
#define NT_TOT   30000
#define N_TETS   (BATCH * NT_TOT)      // 60000
#define EPS_W    0.001f
#define INV2SIG2 200.0f   // 1/(2*0.05^2)

#define TPB          256
#define WORK_BLOCKS  (BATCH * NSURF_N)  // 13780, one vertex per block
#define TETS_PER_BLK 5                  // warps 0..4 each run one tet
                                        // 13780*5 = 68900 slots >= 60000

// Scratch, zero at module load. INVARIANT: both arrays are all-zero on entry
// to kernel_launch; finalize_kernel restores that invariant each call.
// acc = (sem0, sem1, sem2, wsum) -- EPS_W baseline applied in finalize.
__device__ unsigned char g_occ[BATCH * R3];
__device__ float4        g_acc[BATCH * R3];

__device__ __forceinline__ void red_add_f32x4(float4* addr, float x, float y,
                                              float z, float w) {
    asm volatile("red.global.add.v4.f32 [%0], {%1, %2, %3, %4};"
                 :: "l"(addr), "f"(x), "f"(y), "f"(z), "f"(w)
                 : "memory");
}

// ---------------------------------------------------------------------------
// tet occupancy, warp-granular: one warp per (b, tet).
// Barycentric gradients g1,g2,g3 precomputed once; each voxel test = 3 dots.
// ---------------------------------------------------------------------------
__device__ __forceinline__ void tet_work(int gw, int lane,
                                         const float* __restrict__ verts,
                                         const int*   __restrict__ tets) {
    int b = (gw >= NT_TOT) ? 1 : 0;
    int t = gw - b * NT_TOT;

    int4 ti = ((const int4*)tets)[t];
    const float* vb = verts + (size_t)b * NV_TOT * 3;
    const float* p0 = vb + (size_t)ti.x * 3;
    const float* p1 = vb + (size_t)ti.y * 3;
    const float* p2 = vb + (size_t)ti.z * 3;
    const float* p3 = vb + (size_t)ti.w * 3;

    float ax = p0[0], ay = p0[1], az = p0[2];
    float bxv = p1[0], byv = p1[1], bzv = p1[2];
    float cxv = p2[0], cyv = p2[1], czv = p2[2];
    float dxv = p3[0], dyv = p3[1], dzv = p3[2];

    float e1x = bxv - ax, e1y = byv - ay, e1z = bzv - az;
    float e2x = cxv - ax, e2y = cyv - ay, e2z = czv - az;
    float e3x = dxv - ax, e3y = dyv - ay, e3z = dzv - az;

    float c23x = e2y * e3z - e2z * e3y;
    float c23y = e2z * e3x - e2x * e3z;
    float c23z = e2x * e3y - e2y * e3x;

    float vol6 = e1x * c23x + e1y * c23y + e1z * c23z;
    if (!(fabsf(vol6) > 1e-12f)) return;
    float iv = 1.0f / vol6;

    float g1x = c23x * iv, g1y = c23y * iv, g1z = c23z * iv;
    float g2x = (e3y * e1z - e3z * e1y) * iv;   // cross(e3,e1)*iv
    float g2y = (e3z * e1x - e3x * e1z) * iv;
    float g2z = (e3x * e1y - e3y * e1x) * iv;
    float g3x = (e1y * e2z - e1z * e2y) * iv;   // cross(e1,e2)*iv
    float g3y = (e1z * e2x - e1x * e2z) * iv;
    float g3z = (e1x * e2y - e1y * e2x) * iv;

    int anx  = (int)floorf(fminf(fminf(ax, bxv), fminf(cxv, dxv)) * (float)R);
    int any_ = (int)floorf(fminf(fminf(ay, byv), fminf(cyv, dyv)) * (float)R);
    int anz  = (int)floorf(fminf(fminf(az, bzv), fminf(czv, dzv)) * (float)R);

    unsigned char* occb = g_occ + b * R3;

    #pragma unroll
    for (int k = 0; k < 4; k++) {
        int j = lane + k * 32;
        if (j >= 125) break;
        int t0 = anx + j % 5;                   // x-fastest
        int t1 = any_ + (j / 5) % 5;
        int t2 = anz + j / 25;
        if ((unsigned)t0 >= R || (unsigned)t1 >= R || (unsigned)t2 >= R) continue;

        float px = ((float)t0 + 0.5f) * (1.0f / (float)R) - ax;
        float py = ((float)t1 + 0.5f) * (1.0f / (float)R) - ay;
        float pz = ((float)t2 + 0.5f) * (1.0f / (float)R) - az;

        float l1 = px * g1x + py * g1y + pz * g1z;
        float l2 = px * g2x + py * g2y + pz * g2z;
        float l3 = px * g3x + py * g3y + pz * g3z;

        if (l1 >= 0.0f && l2 >= 0.0f && l3 >= 0.0f && (l1 + l2 + l3) <= 1.0f) {
            occb[(t2 * R + t1) * R + t0] = 1;
        }
    }
}

// ---------------------------------------------------------------------------
// surface splat: one (b, vertex) per block; thread covers voxel j = tid and
// j = tid + 256 of the 7^3 window (x-fastest). One no-return float4
// reduction per voxel: (w*c0, w*c1, w*c2, w).
// ---------------------------------------------------------------------------
__device__ __forceinline__ void splat_voxel(int j, int bx, int by, int bz,
                                            float vx, float vy, float vz,
                                            float c0, float c1, float c2,
                                            float4* __restrict__ accb) {
    int s0 = bx + j % 7 - 3;          // x fastest -> contiguous in memory
    int s1 = by + (j / 7) % 7 - 3;
    int s2 = bz + j / 49 - 3;
    if ((unsigned)s0 >= R || (unsigned)s1 >= R || (unsigned)s2 >= R) return;

    float dx = ((float)s0 + 0.5f) * (1.0f / (float)R) - vx;
    float dy = ((float)s1 + 0.5f) * (1.0f / (float)R) - vy;
    float dz = ((float)s2 + 0.5f) * (1.0f / (float)R) - vz;
    float d2 = dx * dx + dy * dy + dz * dz;
    float w = __expf(-d2 * INV2SIG2);

    int vox = (s2 * R + s1) * R + s0;
    red_add_f32x4(&accb[vox], w * c0, w * c1, w * c2, w);
}

// ---------------------------------------------------------------------------
// fused work kernel: every block = one splat vertex (all 256 threads issue
// no-return reductions) + up to 5 tets (warps 0..4, one tet per warp) that
// execute ALU work while the block's splat atomics drain through L2.
// ---------------------------------------------------------------------------
__global__ void __launch_bounds__(TPB)
work_kernel(const float* __restrict__ verts,
            const float* __restrict__ code,
            const int*   __restrict__ tets) {
    int blk = blockIdx.x;
    int tid = threadIdx.x;

    // ---- splat phase: issue the reductions (no-return -> no result stall)
    {
        int b = (blk >= NSURF_N) ? 1 : 0;
        int v = blk - b * NSURF_N;

        const float* vp = verts + ((size_t)b * NV_TOT + v) * 3;
        float vx = vp[0], vy = vp[1], vz = vp[2];
        const float* cp = code + ((size_t)b * NSURF_N + v) * 3;
        float c0 = cp[0], c1 = cp[1], c2 = cp[2];

        int bx = (int)floorf(vx * (float)R);
        int by = (int)floorf(vy * (float)R);
        int bz = (int)floorf(vz * (float)R);

        float4* accb = g_acc + b * R3;

        splat_voxel(tid, bx, by, bz, vx, vy, vz, c0, c1, c2, accb);
        if (tid < 343 - TPB)
            splat_voxel(tid + TPB, bx, by, bz, vx, vy, vz, c0, c1, c2, accb);
    }

    // ---- tet phase: warps 0..4 each process one tet while atomics drain
    int warp = tid >> 5;
    if (warp < TETS_PER_BLK) {
        int gw = blk * TETS_PER_BLK + warp;
        if (gw < N_TETS)
            tet_work(gw, tid & 31, verts, tets);
    }
}

// ---------------------------------------------------------------------------
// finalize: out[b,c,vox] = acc.c / (acc.w + EPS_W) * occ, then reset acc/occ
// to zero. One 4-voxel group per thread. FAST PATH: if all 4 occ bytes are
// zero the output is zero regardless of acc, so skip the 64B acc read (and
// the occ rewrite -- it is already zero); only the zero-stores remain.
// ---------------------------------------------------------------------------
__global__ void finalize_kernel(float* __restrict__ out) {
    int i = blockIdx.x * blockDim.x + threadIdx.x;   // 4-voxel group
    if (i >= BATCH * R3 / 4) return;
    int gi  = i * 4;
    int b   = gi >> 21;
    int vox = gi & (R3 - 1);

    unsigned int ocw = ((const unsigned int*)g_occ)[i];
    float4* a = g_acc + gi;
    float* ob = out + (size_t)b * 3 * R3 + vox;
    float4 z = make_float4(0.0f, 0.0f, 0.0f, 0.0f);

    if (ocw == 0u) {
        // occupancy zero for all 4 voxels: out = 0, reset acc, occ already 0
        __stcs((float4*)(ob),          z);
        __stcs((float4*)(ob + R3),     z);
        __stcs((float4*)(ob + 2 * R3), z);
        a[0] = z; a[1] = z; a[2] = z; a[3] = z;
        return;
    }

    uchar4 oc = *(const uchar4*)&ocw;
    float4 a0 = a[0], a1 = a[1], a2 = a[2], a3 = a[3];

    float s0 = __fdividef((float)oc.x, a0.w + EPS_W);
    float s1 = __fdividef((float)oc.y, a1.w + EPS_W);
    float s2 = __fdividef((float)oc.z, a2.w + EPS_W);
    float s3 = __fdividef((float)oc.w, a3.w + EPS_W);

    __stcs((float4*)(ob),
           make_float4(a0.x * s0, a1.x * s1, a2.x * s2, a3.x * s3));
    __stcs((float4*)(ob + R3),
           make_float4(a0.y * s0, a1.y * s1, a2.y * s2, a3.y * s3));
    __stcs((float4*)(ob + 2 * R3),
           make_float4(a0.z * s0, a1.z * s1, a2.z * s2, a3.z * s3));

    // restore the all-zero invariant for the next launch
    a[0] = z; a[1] = z; a[2] = z; a[3] = z;
    ((unsigned int*)g_occ)[i] = 0u;
}

// ---------------------------------------------------------------------------
extern "C" void kernel_launch(void* const* d_in, const int* in_sizes, int n_in,
                              void* d_out, int out_size) {
    const float* smpl_vertices = (const float*)d_in[0]; // (2, 7700, 3)
    const float* vertex_code   = (const float*)d_in[1]; // (2, 6890, 3)
    // d_in[2] = face_indices — dead code in the reference, unused.
    const int*   tet_indices   = (const int*)d_in[3];   // (30000, 4)
    float* out = (float*)d_out;                         // (2, 3, 128, 128, 128)

    work_kernel<<<WORK_BLOCKS, TPB>>>(smpl_vertices, vertex_code, tet_indices);
    {
        int n = BATCH * R3 / 4;
        finalize_kernel<<<(n + TPB - 1) / TPB, TPB>>>(out);
    }
}